// round 1
// baseline (speedup 1.0000x reference)
#include <cuda_runtime.h>
#include <math.h>

// Problem constants
#define BB 8
#define NN 1024
#define CC 768
#define HH 12
#define DD 64
#define PP 16
#define THREE_C 2304
#define MTOT (BB*NN)          // 8192
#define HEADROWS (BB*HH*NN)   // 98304

// Scratch (allocation-free rule: __device__ globals)
__device__ float g_q[BB*HH*NN*DD];    // [b,h,n,d], pre-scaled by D^-0.5
__device__ float g_k[BB*HH*NN*DD];
__device__ float g_v[BB*HH*NN*DD];
__device__ float g_att[MTOT*CC];      // [b,n,h,d] == [B*N, C]

// ---------------------------------------------------------------------------
// SGEMM core: C[m,f] = sum_k A[m,k] * W[f,k]  (A row-major [M,768], W row-major [F,768])
// Tile 128x128x8, 256 threads, 8x8 per thread (two 4x4 groups, conflict-free frags).
// ---------------------------------------------------------------------------

__global__ __launch_bounds__(256)
void gemm_qkv_kernel(const float* __restrict__ x,
                     const float* __restrict__ w,
                     const float* __restrict__ bias)
{
    __shared__ float As[8][128];
    __shared__ float Bs[8][128];

    const int bm = blockIdx.y * 128;   // m tile (64 tiles)
    const int bn = blockIdx.x * 128;   // f tile (18 tiles)
    const int tid = threadIdx.x;

    const int lrow = tid >> 1;         // 0..127
    const int lcol = (tid & 1) * 4;    // 0 or 4
    const float* ap = x + (bm + lrow) * 768 + lcol;
    const float* bp = w + (bn + lrow) * 768 + lcol;

    const int tx = tid & 15;           // n dir
    const int ty = tid >> 4;           // m dir

    float acc[8][8];
    #pragma unroll
    for (int i = 0; i < 8; i++)
        #pragma unroll
        for (int j = 0; j < 8; j++) acc[i][j] = 0.f;

    for (int k0 = 0; k0 < 768; k0 += 8) {
        float4 a4 = *(const float4*)(ap + k0);
        float4 b4 = *(const float4*)(bp + k0);
        __syncthreads();
        As[lcol+0][lrow] = a4.x; As[lcol+1][lrow] = a4.y;
        As[lcol+2][lrow] = a4.z; As[lcol+3][lrow] = a4.w;
        Bs[lcol+0][lrow] = b4.x; Bs[lcol+1][lrow] = b4.y;
        Bs[lcol+2][lrow] = b4.z; Bs[lcol+3][lrow] = b4.w;
        __syncthreads();
        #pragma unroll
        for (int kk = 0; kk < 8; kk++) {
            float a[8], b[8];
            *(float4*)(a)     = *(const float4*)&As[kk][ty*4];
            *(float4*)(a + 4) = *(const float4*)&As[kk][64 + ty*4];
            *(float4*)(b)     = *(const float4*)&Bs[kk][tx*4];
            *(float4*)(b + 4) = *(const float4*)&Bs[kk][64 + tx*4];
            #pragma unroll
            for (int i = 0; i < 8; i++)
                #pragma unroll
                for (int j = 0; j < 8; j++)
                    acc[i][j] = fmaf(a[i], b[j], acc[i][j]);
        }
    }

    // Scatter epilogue: f -> (t, h, d); m -> (b, n). Store q scaled by 0.125.
    #pragma unroll
    for (int i = 0; i < 8; i++) {
        const int m = bm + ((i < 4) ? (ty*4 + i) : (64 + ty*4 + i - 4));
        const int bidx = m >> 10;
        const int n    = m & 1023;
        #pragma unroll
        for (int j = 0; j < 8; j++) {
            const int f = bn + ((j < 4) ? (tx*4 + j) : (64 + tx*4 + j - 4));
            float val = acc[i][j] + __ldg(&bias[f]);
            const int t = f / 768;
            const int r = f - t * 768;
            const int h = r >> 6;
            const int d = r & 63;
            const int dst = (((bidx*HH + h)*NN) + n)*DD + d;
            if (t == 0)      g_q[dst] = val * 0.125f;   // D^-0.5 folded in
            else if (t == 1) g_k[dst] = val;
            else             g_v[dst] = val;
        }
    }
}

__global__ __launch_bounds__(256)
void gemm_proj_kernel(const float* __restrict__ w,
                      const float* __restrict__ bias,
                      float* __restrict__ out)
{
    __shared__ float As[8][128];
    __shared__ float Bs[8][128];

    const int bm = blockIdx.y * 128;   // 64 tiles
    const int bn = blockIdx.x * 128;   // 6 tiles
    const int tid = threadIdx.x;

    const int lrow = tid >> 1;
    const int lcol = (tid & 1) * 4;
    const float* ap = g_att + (bm + lrow) * 768 + lcol;
    const float* bp = w + (bn + lrow) * 768 + lcol;

    const int tx = tid & 15;
    const int ty = tid >> 4;

    float acc[8][8];
    #pragma unroll
    for (int i = 0; i < 8; i++)
        #pragma unroll
        for (int j = 0; j < 8; j++) acc[i][j] = 0.f;

    for (int k0 = 0; k0 < 768; k0 += 8) {
        float4 a4 = *(const float4*)(ap + k0);
        float4 b4 = *(const float4*)(bp + k0);
        __syncthreads();
        As[lcol+0][lrow] = a4.x; As[lcol+1][lrow] = a4.y;
        As[lcol+2][lrow] = a4.z; As[lcol+3][lrow] = a4.w;
        Bs[lcol+0][lrow] = b4.x; Bs[lcol+1][lrow] = b4.y;
        Bs[lcol+2][lrow] = b4.z; Bs[lcol+3][lrow] = b4.w;
        __syncthreads();
        #pragma unroll
        for (int kk = 0; kk < 8; kk++) {
            float a[8], b[8];
            *(float4*)(a)     = *(const float4*)&As[kk][ty*4];
            *(float4*)(a + 4) = *(const float4*)&As[kk][64 + ty*4];
            *(float4*)(b)     = *(const float4*)&Bs[kk][tx*4];
            *(float4*)(b + 4) = *(const float4*)&Bs[kk][64 + tx*4];
            #pragma unroll
            for (int i = 0; i < 8; i++)
                #pragma unroll
                for (int j = 0; j < 8; j++)
                    acc[i][j] = fmaf(a[i], b[j], acc[i][j]);
        }
    }

    #pragma unroll
    for (int i = 0; i < 8; i++) {
        const int m = bm + ((i < 4) ? (ty*4 + i) : (64 + ty*4 + i - 4));
        #pragma unroll
        for (int j = 0; j < 8; j++) {
            const int f = bn + ((j < 4) ? (tx*4 + j) : (64 + tx*4 + j - 4));
            out[m * 768 + f] = acc[i][j] + __ldg(&bias[f]);
        }
    }
}

// ---------------------------------------------------------------------------
// Flash attention with prefix KV.
// grid = (N/128, H, B); 128 threads; one query row per thread.
// Online softmax with lazy rescale (rescale only when max changes).
// ---------------------------------------------------------------------------
#define KPAD 68   // row pad (float4-aligned: 272B) to spread smem banks

__global__ __launch_bounds__(128)
void attn_kernel(const float* __restrict__ pk, const float* __restrict__ pv)
{
    const int b = blockIdx.z;
    const int h = blockIdx.y;
    const int n = blockIdx.x * 128 + threadIdx.x;

    __shared__ float ks[64][KPAD];
    __shared__ float vs[64][KPAD];

    const float* qbase = g_q + (((b*HH + h)*NN) + n) * DD;
    float qr[64];
    #pragma unroll
    for (int i = 0; i < 16; i++)
        *(float4*)(qr + 4*i) = *(const float4*)(qbase + 4*i);

    float mrun = -INFINITY;
    float lrun = 0.f;
    float o[64];
    #pragma unroll
    for (int d = 0; d < 64; d++) o[d] = 0.f;

    const float* kb = g_k + ((b*HH + h) * NN) * DD;
    const float* vb = g_v + ((b*HH + h) * NN) * DD;

    for (int tile = 0; tile <= 16; ++tile) {
        int nk;
        __syncthreads();
        if (tile == 0) {
            nk = PP;  // 16 prefix keys
            for (int i = threadIdx.x; i < PP * 16; i += 128) {
                const int key = i >> 4;
                const int dc  = (i & 15) * 4;
                *(float4*)&ks[key][dc] = *(const float4*)(pk + key*CC + h*DD + dc);
                *(float4*)&vs[key][dc] = *(const float4*)(pv + key*CC + h*DD + dc);
            }
        } else {
            nk = 64;
            const float* kt = kb + (tile - 1) * 64 * DD;
            const float* vt = vb + (tile - 1) * 64 * DD;
            for (int i = threadIdx.x; i < 64 * 16; i += 128) {
                const int key = i >> 4;
                const int dc  = (i & 15) * 4;
                *(float4*)&ks[key][dc] = *(const float4*)(kt + key*DD + dc);
                *(float4*)&vs[key][dc] = *(const float4*)(vt + key*DD + dc);
            }
        }
        __syncthreads();

        for (int j = 0; j < nk; ++j) {
            float s0 = 0.f, s1 = 0.f, s2 = 0.f, s3 = 0.f;
            #pragma unroll
            for (int d = 0; d < 64; d += 4) {
                float4 kv = *(const float4*)&ks[j][d];   // warp-wide broadcast
                s0 = fmaf(qr[d+0], kv.x, s0);
                s1 = fmaf(qr[d+1], kv.y, s1);
                s2 = fmaf(qr[d+2], kv.z, s2);
                s3 = fmaf(qr[d+3], kv.w, s3);
            }
            const float s = (s0 + s1) + (s2 + s3);   // q pre-scaled by D^-0.5

            if (s <= mrun) {
                const float p = __expf(s - mrun);
                lrun += p;
                #pragma unroll
                for (int d = 0; d < 64; d += 4) {
                    float4 vv = *(const float4*)&vs[j][d];
                    o[d+0] = fmaf(p, vv.x, o[d+0]);
                    o[d+1] = fmaf(p, vv.y, o[d+1]);
                    o[d+2] = fmaf(p, vv.z, o[d+2]);
                    o[d+3] = fmaf(p, vv.w, o[d+3]);
                }
            } else {
                const float f = __expf(mrun - s);    // exp(-inf)=0 handles first key
                mrun = s;
                lrun = lrun * f + 1.f;
                #pragma unroll
                for (int d = 0; d < 64; d += 4) {
                    float4 vv = *(const float4*)&vs[j][d];
                    o[d+0] = fmaf(o[d+0], f, vv.x);
                    o[d+1] = fmaf(o[d+1], f, vv.y);
                    o[d+2] = fmaf(o[d+2], f, vv.z);
                    o[d+3] = fmaf(o[d+3], f, vv.w);
                }
            }
        }
    }

    const float inv = 1.f / lrun;
    float* outp = g_att + (((b*NN + n)*HH) + h) * DD;   // [b,n,h,d] == [B*N, C]
    #pragma unroll
    for (int d = 0; d < 64; d += 4) {
        float4 t;
        t.x = o[d+0] * inv; t.y = o[d+1] * inv;
        t.z = o[d+2] * inv; t.w = o[d+3] * inv;
        *(float4*)(outp + d) = t;
    }
}

// ---------------------------------------------------------------------------

extern "C" void kernel_launch(void* const* d_in, const int* in_sizes, int n_in,
                              void* d_out, int out_size)
{
    const float* x      = (const float*)d_in[0];
    const float* qkv_w  = (const float*)d_in[1];
    const float* qkv_b  = (const float*)d_in[2];
    const float* proj_w = (const float*)d_in[3];
    const float* proj_b = (const float*)d_in[4];
    const float* pk     = (const float*)d_in[5];
    const float* pv     = (const float*)d_in[6];
    float* out = (float*)d_out;

    dim3 g1(THREE_C/128, MTOT/128);      // 18 x 64
    gemm_qkv_kernel<<<g1, 256>>>(x, qkv_w, qkv_b);

    dim3 g2(NN/128, HH, BB);             // 8 x 12 x 8
    attn_kernel<<<g2, 128>>>(pk, pv);

    dim3 g3(CC/128, MTOT/128);           // 6 x 64
    gemm_proj_kernel<<<g3, 256>>>(proj_w, proj_b, out);
}

// round 2
// speedup vs baseline: 2.5341x; 2.5341x over previous
#include <cuda_runtime.h>
#include <math.h>
#include <stdint.h>

// Problem constants
#define BB 8
#define NN 1024
#define CC 768
#define HH 12
#define DD 64
#define PP 16
#define THREE_C 2304
#define MTOT (BB*NN)          // 8192

// Scratch
__device__ float g_q[BB*HH*NN*DD];    // [b,h,n,d], pre-scaled by D^-0.5
__device__ float g_k[BB*HH*NN*DD];
__device__ float g_v[BB*HH*NN*DD];
__device__ float g_att[MTOT*CC];      // [b,n,h,d] == [B*N, C]

// ---------------------------------------------------------------------------
// tf32 helpers
// ---------------------------------------------------------------------------
__device__ __forceinline__ uint32_t f2t(float x) {
    uint32_t r; asm("cvt.rna.tf32.f32 %0, %1;" : "=r"(r) : "f"(x)); return r;
}
__device__ __forceinline__ uint4 cvt4(float4 v) {
    return make_uint4(f2t(v.x), f2t(v.y), f2t(v.z), f2t(v.w));
}
__device__ __forceinline__ void mma_tf32(float* c, const uint32_t* a, const uint32_t* b) {
    asm volatile(
        "mma.sync.aligned.m16n8k8.row.col.f32.tf32.tf32.f32 "
        "{%0,%1,%2,%3}, {%4,%5,%6,%7}, {%8,%9}, {%0,%1,%2,%3};"
        : "+f"(c[0]), "+f"(c[1]), "+f"(c[2]), "+f"(c[3])
        : "r"(a[0]), "r"(a[1]), "r"(a[2]), "r"(a[3]), "r"(b[0]), "r"(b[1]));
}

// ---------------------------------------------------------------------------
// tf32 GEMM core: C[m,f] = sum_k A[m,k] * W[f,k], K=768.
// 128x128 tile, 256 threads (8 warps: 2 m-groups x 4 n-groups),
// per warp 4x4 m16n8 accum tiles. Smem stride 36 words -> conflict-free frags.
// ---------------------------------------------------------------------------
#define KCH 32
#define GST 36    // smem row stride (words); 36 mod 32 = 4

#define GEMM_PROLOG(APTR)                                                     \
    __shared__ uint32_t As[128*GST];                                          \
    __shared__ uint32_t Bs[128*GST];                                          \
    const int tid  = threadIdx.x;                                             \
    const int bm   = blockIdx.y * 128, bn = blockIdx.x * 128;                 \
    const int lane = tid & 31, warp = tid >> 5;                               \
    const int g    = lane >> 2, t = lane & 3;                                 \
    const int wm   = (warp & 1) * 64, wn = (warp >> 1) * 32;                  \
    const int lrow = tid >> 1;                                                \
    const int lc0  = (tid & 1) * 16;                                          \
    const float* ap = (APTR) + (bm + lrow) * 768 + lc0;                       \
    const float* bp = w + (bn + lrow) * 768 + lc0;                            \
    uint32_t* asr = &As[lrow * GST + lc0];                                    \
    uint32_t* bsr = &Bs[lrow * GST + lc0];                                    \
    float acc[4][4][4];                                                       \
    _Pragma("unroll")                                                         \
    for (int i = 0; i < 4; i++)                                               \
        _Pragma("unroll")                                                     \
        for (int j = 0; j < 4; j++)                                           \
            _Pragma("unroll")                                                 \
            for (int c = 0; c < 4; c++) acc[i][j][c] = 0.f;                   \
    for (int k0 = 0; k0 < 768; k0 += KCH) {                                   \
        float4 av[4], bv[4];                                                  \
        _Pragma("unroll")                                                     \
        for (int j = 0; j < 4; j++) {                                         \
            av[j] = *(const float4*)(ap + k0 + 4*j);                          \
            bv[j] = *(const float4*)(bp + k0 + 4*j);                          \
        }                                                                     \
        __syncthreads();                                                      \
        _Pragma("unroll")                                                     \
        for (int j = 0; j < 4; j++) {                                         \
            *(uint4*)&asr[4*j] = cvt4(av[j]);                                 \
            *(uint4*)&bsr[4*j] = cvt4(bv[j]);                                 \
        }                                                                     \
        __syncthreads();                                                      \
        _Pragma("unroll")                                                     \
        for (int ks = 0; ks < 4; ks++) {                                      \
            uint32_t af[4][4], bf[4][2];                                      \
            _Pragma("unroll")                                                 \
            for (int mt = 0; mt < 4; mt++) {                                  \
                const uint32_t* p0 = &As[(wm + mt*16 + g    )*GST + ks*8 + t];\
                const uint32_t* p1 = &As[(wm + mt*16 + g + 8)*GST + ks*8 + t];\
                af[mt][0] = p0[0]; af[mt][2] = p0[4];                         \
                af[mt][1] = p1[0]; af[mt][3] = p1[4];                         \
            }                                                                 \
            _Pragma("unroll")                                                 \
            for (int nt = 0; nt < 4; nt++) {                                  \
                const uint32_t* p = &Bs[(wn + nt*8 + g)*GST + ks*8 + t];      \
                bf[nt][0] = p[0]; bf[nt][1] = p[4];                           \
            }                                                                 \
            _Pragma("unroll")                                                 \
            for (int mt = 0; mt < 4; mt++)                                    \
                _Pragma("unroll")                                             \
                for (int nt = 0; nt < 4; nt++)                                \
                    mma_tf32(acc[mt][nt], af[mt], bf[nt]);                    \
        }                                                                     \
    }

__global__ __launch_bounds__(256)
void gemm_qkv_tc(const float* __restrict__ x,
                 const float* __restrict__ w,
                 const float* __restrict__ bias)
{
    GEMM_PROLOG(x)
    // Scatter epilogue: f -> (t3, h, d); m -> (b, n). q scaled by D^-0.5.
    #pragma unroll
    for (int mt = 0; mt < 4; mt++) {
        #pragma unroll
        for (int half = 0; half < 2; half++) {
            const int m    = bm + wm + mt*16 + g + half*8;
            const int bidx = m >> 10;
            const int n    = m & 1023;
            #pragma unroll
            for (int nt = 0; nt < 4; nt++) {
                #pragma unroll
                for (int c2 = 0; c2 < 2; c2++) {
                    const int f = bn + wn + nt*8 + 2*t + c2;
                    float val = acc[mt][nt][half*2 + c2] + __ldg(&bias[f]);
                    const int t3 = f / 768;
                    const int r  = f - t3 * 768;
                    const int h  = r >> 6;
                    const int d  = r & 63;
                    const int dst = (((bidx*HH + h)*NN) + n)*DD + d;
                    if (t3 == 0)      g_q[dst] = val * 0.125f;
                    else if (t3 == 1) g_k[dst] = val;
                    else              g_v[dst] = val;
                }
            }
        }
    }
}

__global__ __launch_bounds__(256)
void gemm_proj_tc(const float* __restrict__ w,
                  const float* __restrict__ bias,
                  float* __restrict__ out)
{
    GEMM_PROLOG(g_att)
    #pragma unroll
    for (int mt = 0; mt < 4; mt++) {
        #pragma unroll
        for (int half = 0; half < 2; half++) {
            const int m = bm + wm + mt*16 + g + half*8;
            #pragma unroll
            for (int nt = 0; nt < 4; nt++) {
                const int f = bn + wn + nt*8 + 2*t;
                float2 v;
                v.x = acc[mt][nt][half*2 + 0] + __ldg(&bias[f]);
                v.y = acc[mt][nt][half*2 + 1] + __ldg(&bias[f + 1]);
                *(float2*)&out[m*768 + f] = v;
            }
        }
    }
}

// ---------------------------------------------------------------------------
// tf32 flash attention with prefix KV.
// grid = (N/64, H, B); 128 threads (4 warps), 16 query rows per warp.
// K tile stride 68, V tile stride 72 -> conflict-free B-frag loads.
// ---------------------------------------------------------------------------
#define KSTR 68
#define VSTR 72

template<int NBV>
__device__ __forceinline__ void attn_tile(
    const uint32_t* __restrict__ ksm, const uint32_t* __restrict__ vsm,
    const uint32_t qf[8][4], float of[8][4],
    float& m_lo, float& m_hi, float& l_lo, float& l_hi, int lane)
{
    const int g = lane >> 2, t = lane & 3;
    const int base = lane & ~3;

    // --- S = Q @ K^T (per warp 16 x 8*NBV) ---
    float sf[NBV][4];
    #pragma unroll
    for (int nb = 0; nb < NBV; nb++)
        #pragma unroll
        for (int c = 0; c < 4; c++) sf[nb][c] = 0.f;

    #pragma unroll
    for (int ksx = 0; ksx < 8; ksx++) {
        uint32_t bf[NBV][2];
        #pragma unroll
        for (int nb = 0; nb < NBV; nb++) {
            const uint32_t* p = &ksm[(nb*8 + g)*KSTR + ksx*8 + t];
            bf[nb][0] = p[0]; bf[nb][1] = p[4];
        }
        #pragma unroll
        for (int nb = 0; nb < NBV; nb++)
            mma_tf32(sf[nb], qf[ksx], bf[nb]);
    }

    // --- online softmax (rows g and g+8 per thread) ---
    float mx0 = -INFINITY, mx1 = -INFINITY;
    #pragma unroll
    for (int nb = 0; nb < NBV; nb++) {
        mx0 = fmaxf(mx0, fmaxf(sf[nb][0], sf[nb][1]));
        mx1 = fmaxf(mx1, fmaxf(sf[nb][2], sf[nb][3]));
    }
    mx0 = fmaxf(mx0, __shfl_xor_sync(0xFFFFFFFFu, mx0, 1));
    mx0 = fmaxf(mx0, __shfl_xor_sync(0xFFFFFFFFu, mx0, 2));
    mx1 = fmaxf(mx1, __shfl_xor_sync(0xFFFFFFFFu, mx1, 1));
    mx1 = fmaxf(mx1, __shfl_xor_sync(0xFFFFFFFFu, mx1, 2));

    const float nm0 = fmaxf(m_lo, mx0), nm1 = fmaxf(m_hi, mx1);
    const float a0  = __expf(m_lo - nm0), a1 = __expf(m_hi - nm1);
    m_lo = nm0; m_hi = nm1;

    float s0 = 0.f, s1 = 0.f;
    #pragma unroll
    for (int nb = 0; nb < NBV; nb++) {
        sf[nb][0] = __expf(sf[nb][0] - nm0); s0 += sf[nb][0];
        sf[nb][1] = __expf(sf[nb][1] - nm0); s0 += sf[nb][1];
        sf[nb][2] = __expf(sf[nb][2] - nm1); s1 += sf[nb][2];
        sf[nb][3] = __expf(sf[nb][3] - nm1); s1 += sf[nb][3];
    }
    s0 += __shfl_xor_sync(0xFFFFFFFFu, s0, 1);
    s0 += __shfl_xor_sync(0xFFFFFFFFu, s0, 2);
    s1 += __shfl_xor_sync(0xFFFFFFFFu, s1, 1);
    s1 += __shfl_xor_sync(0xFFFFFFFFu, s1, 2);
    l_lo = l_lo * a0 + s0;
    l_hi = l_hi * a1 + s1;

    #pragma unroll
    for (int nb = 0; nb < 8; nb++) {
        of[nb][0] *= a0; of[nb][1] *= a0;
        of[nb][2] *= a1; of[nb][3] *= a1;
    }

    // --- O += P @ V ---
    #pragma unroll
    for (int ksx = 0; ksx < NBV; ksx++) {
        // accum-layout -> A-layout transpose via intra-quad shuffles
        float x0 = __shfl_sync(0xFFFFFFFFu, sf[ksx][0], base + (t >> 1));
        float x1 = __shfl_sync(0xFFFFFFFFu, sf[ksx][1], base + (t >> 1));
        float y0 = __shfl_sync(0xFFFFFFFFu, sf[ksx][0], base + (t >> 1) + 2);
        float y1 = __shfl_sync(0xFFFFFFFFu, sf[ksx][1], base + (t >> 1) + 2);
        float z0 = __shfl_sync(0xFFFFFFFFu, sf[ksx][2], base + (t >> 1));
        float z1 = __shfl_sync(0xFFFFFFFFu, sf[ksx][3], base + (t >> 1));
        float w0 = __shfl_sync(0xFFFFFFFFu, sf[ksx][2], base + (t >> 1) + 2);
        float w1 = __shfl_sync(0xFFFFFFFFu, sf[ksx][3], base + (t >> 1) + 2);
        uint32_t pa[4];
        pa[0] = f2t((t & 1) ? x1 : x0);
        pa[2] = f2t((t & 1) ? y1 : y0);
        pa[1] = f2t((t & 1) ? z1 : z0);
        pa[3] = f2t((t & 1) ? w1 : w0);

        #pragma unroll
        for (int nb = 0; nb < 8; nb++) {
            uint32_t vb[2];
            const uint32_t* p = &vsm[(ksx*8 + t)*VSTR + nb*8 + g];
            vb[0] = p[0];
            vb[1] = p[4*VSTR];
            mma_tf32(of[nb], pa, vb);
        }
    }
}

__global__ __launch_bounds__(128)
void attn_tc(const float* __restrict__ pk, const float* __restrict__ pv)
{
    __shared__ uint32_t ksm[64*KSTR];
    __shared__ uint32_t vsm[64*VSTR];

    const int b = blockIdx.z, h = blockIdx.y;
    const int tid = threadIdx.x, lane = tid & 31, warp = tid >> 5;
    const int g = lane >> 2, t = lane & 3;
    const int qw = blockIdx.x*64 + warp*16;   // warp's query base

    // Q fragments (resident all kernel), q already pre-scaled by D^-0.5
    const float* qb = g_q + (((b*HH + h)*NN) + qw) * DD;
    uint32_t qf[8][4];
    #pragma unroll
    for (int ksx = 0; ksx < 8; ksx++) {
        qf[ksx][0] = f2t(qb[ g     *64 + ksx*8 + t    ]);
        qf[ksx][1] = f2t(qb[(g + 8)*64 + ksx*8 + t    ]);
        qf[ksx][2] = f2t(qb[ g     *64 + ksx*8 + t + 4]);
        qf[ksx][3] = f2t(qb[(g + 8)*64 + ksx*8 + t + 4]);
    }

    float of[8][4];
    #pragma unroll
    for (int nb = 0; nb < 8; nb++)
        #pragma unroll
        for (int c = 0; c < 4; c++) of[nb][c] = 0.f;
    float m_lo = -INFINITY, m_hi = -INFINITY, l_lo = 0.f, l_hi = 0.f;

    const float* kb = g_k + ((b*HH + h) * NN) * DD;
    const float* vb = g_v + ((b*HH + h) * NN) * DD;

    // --- prefix tile: 16 keys ---
    {
        const int prow = tid >> 3;            // 0..15
        const int pcol = (tid & 7) * 8;       // 0..56
        const float* kp = pk + prow*CC + h*DD + pcol;
        const float* vp = pv + prow*CC + h*DD + pcol;
        *(uint4*)&ksm[prow*KSTR + pcol    ] = cvt4(*(const float4*)(kp));
        *(uint4*)&ksm[prow*KSTR + pcol + 4] = cvt4(*(const float4*)(kp + 4));
        *(uint4*)&vsm[prow*VSTR + pcol    ] = cvt4(*(const float4*)(vp));
        *(uint4*)&vsm[prow*VSTR + pcol + 4] = cvt4(*(const float4*)(vp + 4));
    }
    __syncthreads();
    attn_tile<2>(ksm, vsm, qf, of, m_lo, m_hi, l_lo, l_hi, lane);

    // --- 16 full tiles of 64 keys ---
    const int trow = tid >> 1;                // 0..63
    const int tc0  = (tid & 1) * 32;
    for (int tile = 0; tile < 16; tile++) {
        __syncthreads();   // previous compute done before overwrite
        const float* kt = kb + (tile*64 + trow)*DD + tc0;
        const float* vt = vb + (tile*64 + trow)*DD + tc0;
        #pragma unroll
        for (int j = 0; j < 8; j++) {
            *(uint4*)&ksm[trow*KSTR + tc0 + 4*j] = cvt4(*(const float4*)(kt + 4*j));
            *(uint4*)&vsm[trow*VSTR + tc0 + 4*j] = cvt4(*(const float4*)(vt + 4*j));
        }
        __syncthreads();
        attn_tile<8>(ksm, vsm, qf, of, m_lo, m_hi, l_lo, l_hi, lane);
    }

    // --- epilogue: normalize + write [b,n,h,d] ---
    const float inv0 = 1.f / l_lo, inv1 = 1.f / l_hi;
    #pragma unroll
    for (int nb = 0; nb < 8; nb++) {
        const int d = nb*8 + 2*t;
        float2 lo, hi;
        lo.x = of[nb][0]*inv0; lo.y = of[nb][1]*inv0;
        hi.x = of[nb][2]*inv1; hi.y = of[nb][3]*inv1;
        *(float2*)&g_att[((b*NN + qw + g    )*HH + h)*DD + d] = lo;
        *(float2*)&g_att[((b*NN + qw + g + 8)*HH + h)*DD + d] = hi;
    }
}

// ---------------------------------------------------------------------------

extern "C" void kernel_launch(void* const* d_in, const int* in_sizes, int n_in,
                              void* d_out, int out_size)
{
    const float* x      = (const float*)d_in[0];
    const float* qkv_w  = (const float*)d_in[1];
    const float* qkv_b  = (const float*)d_in[2];
    const float* proj_w = (const float*)d_in[3];
    const float* proj_b = (const float*)d_in[4];
    const float* pk     = (const float*)d_in[5];
    const float* pv     = (const float*)d_in[6];
    float* out = (float*)d_out;

    dim3 g1(THREE_C/128, MTOT/128);      // 18 x 64
    gemm_qkv_tc<<<g1, 256>>>(x, qkv_w, qkv_b);

    dim3 g2(NN/64, HH, BB);              // 16 x 12 x 8
    attn_tc<<<g2, 128>>>(pk, pv);

    dim3 g3(CC/128, MTOT/128);           // 6 x 64
    gemm_proj_tc<<<g3, 256>>>(proj_w, proj_b, out);
}

// round 3
// speedup vs baseline: 2.8867x; 1.1391x over previous
#include <cuda_runtime.h>
#include <math.h>
#include <stdint.h>

// Problem constants
#define BB 8
#define NN 1024
#define CC 768
#define HH 12
#define DD 64
#define PP 16
#define THREE_C 2304
#define MTOT (BB*NN)          // 8192

// Scratch (__device__ globals; no allocation allowed)
__device__ float g_q[BB*HH*NN*DD];     // [b,h,n,d], pre-scaled, tf32-rounded
__device__ float g_k[BB*HH*NN*DD];     // tf32-rounded
__device__ float g_v[BB*HH*NN*DD];     // tf32-rounded
__device__ float g_att[MTOT*CC];       // [b,n,h,d], tf32-rounded
__device__ float g_xt[MTOT*CC];        // x, tf32-rounded
__device__ float g_wt[THREE_C*CC];     // qkv_w, tf32-rounded
__device__ float g_pwt[CC*CC];         // proj_w, tf32-rounded

// ---------------------------------------------------------------------------
// helpers
// ---------------------------------------------------------------------------
__device__ __forceinline__ uint32_t f2t(float x) {
    uint32_t r; asm("cvt.rna.tf32.f32 %0, %1;" : "=r"(r) : "f"(x)); return r;
}
__device__ __forceinline__ float rnd(float x) { return __uint_as_float(f2t(x)); }

__device__ __forceinline__ void mma_tf32(float* c, const uint32_t* a, const uint32_t* b) {
    asm volatile(
        "mma.sync.aligned.m16n8k8.row.col.f32.tf32.tf32.f32 "
        "{%0,%1,%2,%3}, {%4,%5,%6,%7}, {%8,%9}, {%0,%1,%2,%3};"
        : "+f"(c[0]), "+f"(c[1]), "+f"(c[2]), "+f"(c[3])
        : "r"(a[0]), "r"(a[1]), "r"(a[2]), "r"(a[3]), "r"(b[0]), "r"(b[1]));
}
__device__ __forceinline__ void cpa16(uint32_t dst, const void* src) {
    asm volatile("cp.async.cg.shared.global [%0], [%1], 16;" :: "r"(dst), "l"(src));
}
#define CP_COMMIT() asm volatile("cp.async.commit_group;")
#define CP_WAIT(N)  asm volatile("cp.async.wait_group %0;" :: "n"(N))

// ---------------------------------------------------------------------------
// pre-convert: out[i] = tf32_rna(in[i])
// ---------------------------------------------------------------------------
__global__ void cvt_tf32(const float4* __restrict__ in, float4* __restrict__ out, int n4) {
    int i = blockIdx.x * blockDim.x + threadIdx.x;
    if (i < n4) {
        float4 v = in[i];
        v.x = rnd(v.x); v.y = rnd(v.y); v.z = rnd(v.z); v.w = rnd(v.w);
        out[i] = v;
    }
}

// ---------------------------------------------------------------------------
// tf32 GEMM: C[m,f] = sum_k A[m,k]*W[f,k], K=768, operands pre-rounded.
// 128x128 block tile, 128 threads (4 warps 2x2), 64x64 per warp.
// cp.async 2-stage double buffer. Smem stride GST=36 words (conflict-free).
// ---------------------------------------------------------------------------
#define GST 36
#define STG_W (128*GST)          // words per stage per matrix
#define SMEM_GEMM (4*STG_W*4)    // bytes: 2 stages x (A+B)

#define GEMM_MAIN(APTR, BPTR)                                                  \
    extern __shared__ uint32_t dsm[];                                          \
    uint32_t* As = dsm;                                                        \
    uint32_t* Bsm = dsm + 2*STG_W;                                             \
    const int tid  = threadIdx.x;                                              \
    const int bm   = blockIdx.y * 128, bn = blockIdx.x * 128;                  \
    const int lane = tid & 31, warp = tid >> 5;                                \
    const int g    = lane >> 2, t = lane & 3;                                  \
    const int wm   = (warp & 1) * 64, wn = (warp >> 1) * 64;                   \
    const int lrow = tid >> 1, lc0 = (tid & 1) * 16;                           \
    const float* ap = (APTR) + (size_t)(bm + lrow) * 768 + lc0;                \
    const float* bp = (BPTR) + (size_t)(bn + lrow) * 768 + lc0;                \
    const uint32_t a_u = (uint32_t)__cvta_generic_to_shared(As)                \
                         + (lrow*GST + lc0)*4;                                 \
    const uint32_t b_u = (uint32_t)__cvta_generic_to_shared(Bsm)               \
                         + (lrow*GST + lc0)*4;                                 \
    float acc[4][8][4];                                                        \
    _Pragma("unroll")                                                          \
    for (int i = 0; i < 4; i++)                                                \
        _Pragma("unroll")                                                      \
        for (int j = 0; j < 8; j++)                                            \
            _Pragma("unroll")                                                  \
            for (int c = 0; c < 4; c++) acc[i][j][c] = 0.f;                    \
    /* stage 0 prefetch */                                                     \
    _Pragma("unroll")                                                          \
    for (int r = 0; r < 2; r++)                                                \
        _Pragma("unroll")                                                      \
        for (int j = 0; j < 4; j++) {                                          \
            cpa16(a_u + (r*64*GST + 4*j)*4, ap + r*64*768 + 4*j);              \
            cpa16(b_u + (r*64*GST + 4*j)*4, bp + r*64*768 + 4*j);              \
        }                                                                      \
    CP_COMMIT();                                                               \
    int s = 0;                                                                 \
    for (int k0 = 0; k0 < 768; k0 += 32, s ^= 1) {                             \
        if (k0 + 32 < 768) {                                                   \
            const int so = (s^1)*STG_W*4;                                      \
            _Pragma("unroll")                                                  \
            for (int r = 0; r < 2; r++)                                        \
                _Pragma("unroll")                                              \
                for (int j = 0; j < 4; j++) {                                  \
                    cpa16(a_u + so + (r*64*GST + 4*j)*4,                       \
                          ap + k0 + 32 + r*64*768 + 4*j);                      \
                    cpa16(b_u + so + (r*64*GST + 4*j)*4,                       \
                          bp + k0 + 32 + r*64*768 + 4*j);                      \
                }                                                              \
            CP_COMMIT();                                                       \
            CP_WAIT(1);                                                        \
        } else {                                                               \
            CP_WAIT(0);                                                        \
        }                                                                      \
        __syncthreads();                                                       \
        const uint32_t* Ab = As  + s*STG_W;                                    \
        const uint32_t* Bb = Bsm + s*STG_W;                                    \
        _Pragma("unroll")                                                      \
        for (int ks = 0; ks < 4; ks++) {                                       \
            uint32_t af[4][4], bf[8][2];                                       \
            _Pragma("unroll")                                                  \
            for (int mt = 0; mt < 4; mt++) {                                   \
                const uint32_t* p0 = &Ab[(wm + mt*16 + g    )*GST + ks*8 + t]; \
                const uint32_t* p1 = &Ab[(wm + mt*16 + g + 8)*GST + ks*8 + t]; \
                af[mt][0] = p0[0]; af[mt][2] = p0[4];                          \
                af[mt][1] = p1[0]; af[mt][3] = p1[4];                          \
            }                                                                  \
            _Pragma("unroll")                                                  \
            for (int nt = 0; nt < 8; nt++) {                                   \
                const uint32_t* p = &Bb[(wn + nt*8 + g)*GST + ks*8 + t];       \
                bf[nt][0] = p[0]; bf[nt][1] = p[4];                            \
            }                                                                  \
            _Pragma("unroll")                                                  \
            for (int mt = 0; mt < 4; mt++)                                     \
                _Pragma("unroll")                                              \
                for (int nt = 0; nt < 8; nt++)                                 \
                    mma_tf32(acc[mt][nt], af[mt], bf[nt]);                     \
        }                                                                      \
        __syncthreads();                                                       \
    }

__global__ __launch_bounds__(128)
void gemm_qkv_tc(const float* __restrict__ bias)
{
    GEMM_MAIN(g_xt, g_wt)
    // scatter epilogue: f -> (t3,h,d); m -> (b,n). tf32-round q/k/v.
    #pragma unroll
    for (int mt = 0; mt < 4; mt++) {
        #pragma unroll
        for (int half = 0; half < 2; half++) {
            const int m    = bm + wm + mt*16 + g + half*8;
            const int bidx = m >> 10;
            const int n    = m & 1023;
            #pragma unroll
            for (int nt = 0; nt < 8; nt++) {
                #pragma unroll
                for (int c2 = 0; c2 < 2; c2++) {
                    const int f = bn + wn + nt*8 + 2*t + c2;
                    float val = acc[mt][nt][half*2 + c2] + __ldg(&bias[f]);
                    const int t3 = f / 768;
                    const int r  = f - t3 * 768;
                    const int h  = r >> 6;
                    const int d  = r & 63;
                    const int dst = (((bidx*HH + h)*NN) + n)*DD + d;
                    if (t3 == 0)      g_q[dst] = rnd(val * 0.125f);
                    else if (t3 == 1) g_k[dst] = rnd(val);
                    else              g_v[dst] = rnd(val);
                }
            }
        }
    }
}

__global__ __launch_bounds__(128)
void gemm_proj_tc(const float* __restrict__ bias, float* __restrict__ out)
{
    GEMM_MAIN(g_att, g_pwt)
    #pragma unroll
    for (int mt = 0; mt < 4; mt++) {
        #pragma unroll
        for (int half = 0; half < 2; half++) {
            const int m = bm + wm + mt*16 + g + half*8;
            #pragma unroll
            for (int nt = 0; nt < 8; nt++) {
                const int f = bn + wn + nt*8 + 2*t;
                float2 v;
                v.x = acc[mt][nt][half*2 + 0] + __ldg(&bias[f]);
                v.y = acc[mt][nt][half*2 + 1] + __ldg(&bias[f + 1]);
                *(float2*)&out[(size_t)m*768 + f] = v;
            }
        }
    }
}

// ---------------------------------------------------------------------------
// tf32 flash attention, 128 queries/block (4 warps x 32q), 64-key tiles.
// K smem: [key][perm(d)]; V smem transposed: [d][perm(key)].
// perm(i) = (i>>5)*32 + (i&3)*8 + ((i>>3)&3)*2 + ((i>>2)&1) -> per-thread
// contiguous 128-bit fragment chunks, conflict-free with row stride 68.
// ---------------------------------------------------------------------------
#define AST 68

__device__ __forceinline__ void stage_row(
    const float* __restrict__ kp, const float* __restrict__ vp,
    float* __restrict__ ksm, float* __restrict__ vsmT,
    int row, int half, int pc, bool docvt)
{
    #pragma unroll
    for (int j = 0; j < 8; j++) {
        const int d0 = half*32 + 4*j;
        float4 kv = *(const float4*)(kp + 4*j);
        float4 vv = *(const float4*)(vp + 4*j);
        if (docvt) {
            kv.x = rnd(kv.x); kv.y = rnd(kv.y); kv.z = rnd(kv.z); kv.w = rnd(kv.w);
            vv.x = rnd(vv.x); vv.y = rnd(vv.y); vv.z = rnd(vv.z); vv.w = rnd(vv.w);
        }
        const int base = ((d0 >> 5) << 5) + (((d0 >> 3) & 3) << 1) + ((d0 >> 2) & 1);
        float* kr = ksm + row*AST + base;
        kr[0]  = kv.x; kr[8]  = kv.y; kr[16] = kv.z; kr[24] = kv.w;
        vsmT[(d0+0)*AST + pc] = vv.x;
        vsmT[(d0+1)*AST + pc] = vv.y;
        vsmT[(d0+2)*AST + pc] = vv.z;
        vsmT[(d0+3)*AST + pc] = vv.w;
    }
}

template<int NBV>
__device__ __forceinline__ void attn_tile(
    const float* __restrict__ ksm, const float* __restrict__ vsmT,
    const uint32_t qf[2][8][4], float of[2][8][4],
    float mx[2][2], float ll[2][2], int lane)
{
    const int g = lane >> 2, t = lane & 3;
    const int qb = lane & ~3;

    // --- S = Q @ K^T ---
    float sf[2][NBV][4];
    #pragma unroll
    for (int qt = 0; qt < 2; qt++)
        #pragma unroll
        for (int nb = 0; nb < NBV; nb++)
            #pragma unroll
            for (int c = 0; c < 4; c++) sf[qt][nb][c] = 0.f;

    #pragma unroll
    for (int nb = 0; nb < NBV; nb++) {
        const float* kr = ksm + (nb*8 + g)*AST + t*8;
        float4 c0 = *(const float4*)(kr);
        float4 c1 = *(const float4*)(kr + 4);
        float4 c2 = *(const float4*)(kr + 32);
        float4 c3 = *(const float4*)(kr + 36);
        uint32_t bf[8][2];
        bf[0][0]=__float_as_uint(c0.x); bf[0][1]=__float_as_uint(c0.y);
        bf[1][0]=__float_as_uint(c0.z); bf[1][1]=__float_as_uint(c0.w);
        bf[2][0]=__float_as_uint(c1.x); bf[2][1]=__float_as_uint(c1.y);
        bf[3][0]=__float_as_uint(c1.z); bf[3][1]=__float_as_uint(c1.w);
        bf[4][0]=__float_as_uint(c2.x); bf[4][1]=__float_as_uint(c2.y);
        bf[5][0]=__float_as_uint(c2.z); bf[5][1]=__float_as_uint(c2.w);
        bf[6][0]=__float_as_uint(c3.x); bf[6][1]=__float_as_uint(c3.y);
        bf[7][0]=__float_as_uint(c3.z); bf[7][1]=__float_as_uint(c3.w);
        #pragma unroll
        for (int kx = 0; kx < 8; kx++) {
            mma_tf32(sf[0][nb], qf[0][kx], bf[kx]);
            mma_tf32(sf[1][nb], qf[1][kx], bf[kx]);
        }
    }

    // --- online softmax (4 rows/thread) ---
    #pragma unroll
    for (int qt = 0; qt < 2; qt++) {
        float m0 = -INFINITY, m1 = -INFINITY;
        #pragma unroll
        for (int nb = 0; nb < NBV; nb++) {
            m0 = fmaxf(m0, fmaxf(sf[qt][nb][0], sf[qt][nb][1]));
            m1 = fmaxf(m1, fmaxf(sf[qt][nb][2], sf[qt][nb][3]));
        }
        m0 = fmaxf(m0, __shfl_xor_sync(~0u, m0, 1));
        m0 = fmaxf(m0, __shfl_xor_sync(~0u, m0, 2));
        m1 = fmaxf(m1, __shfl_xor_sync(~0u, m1, 1));
        m1 = fmaxf(m1, __shfl_xor_sync(~0u, m1, 2));
        const float nm0 = fmaxf(mx[qt][0], m0), nm1 = fmaxf(mx[qt][1], m1);
        const float a0 = __expf(mx[qt][0] - nm0), a1 = __expf(mx[qt][1] - nm1);
        mx[qt][0] = nm0; mx[qt][1] = nm1;
        float s0 = 0.f, s1 = 0.f;
        #pragma unroll
        for (int nb = 0; nb < NBV; nb++) {
            sf[qt][nb][0] = __expf(sf[qt][nb][0] - nm0); s0 += sf[qt][nb][0];
            sf[qt][nb][1] = __expf(sf[qt][nb][1] - nm0); s0 += sf[qt][nb][1];
            sf[qt][nb][2] = __expf(sf[qt][nb][2] - nm1); s1 += sf[qt][nb][2];
            sf[qt][nb][3] = __expf(sf[qt][nb][3] - nm1); s1 += sf[qt][nb][3];
        }
        s0 += __shfl_xor_sync(~0u, s0, 1);
        s0 += __shfl_xor_sync(~0u, s0, 2);
        s1 += __shfl_xor_sync(~0u, s1, 1);
        s1 += __shfl_xor_sync(~0u, s1, 2);
        ll[qt][0] = ll[qt][0]*a0 + s0;
        ll[qt][1] = ll[qt][1]*a1 + s1;
        #pragma unroll
        for (int nb = 0; nb < 8; nb++) {
            of[qt][nb][0] *= a0; of[qt][nb][1] *= a0;
            of[qt][nb][2] *= a1; of[qt][nb][3] *= a1;
        }
    }

    // --- transpose P (accum->A layout) in place, tf32-round ---
    #pragma unroll
    for (int qt = 0; qt < 2; qt++) {
        #pragma unroll
        for (int kb = 0; kb < NBV; kb++) {
            float x0 = __shfl_sync(~0u, sf[qt][kb][0], qb + (t>>1));
            float x1 = __shfl_sync(~0u, sf[qt][kb][1], qb + (t>>1));
            float y0 = __shfl_sync(~0u, sf[qt][kb][0], qb + (t>>1) + 2);
            float y1 = __shfl_sync(~0u, sf[qt][kb][1], qb + (t>>1) + 2);
            float z0 = __shfl_sync(~0u, sf[qt][kb][2], qb + (t>>1));
            float z1 = __shfl_sync(~0u, sf[qt][kb][3], qb + (t>>1));
            float w0 = __shfl_sync(~0u, sf[qt][kb][2], qb + (t>>1) + 2);
            float w1 = __shfl_sync(~0u, sf[qt][kb][3], qb + (t>>1) + 2);
            sf[qt][kb][0] = __uint_as_float(f2t((t & 1) ? x1 : x0));
            sf[qt][kb][2] = __uint_as_float(f2t((t & 1) ? y1 : y0));
            sf[qt][kb][1] = __uint_as_float(f2t((t & 1) ? z1 : z0));
            sf[qt][kb][3] = __uint_as_float(f2t((t & 1) ? w1 : w0));
        }
    }

    // --- O += P @ V ---
    #pragma unroll
    for (int nb = 0; nb < 8; nb++) {
        const float* vr = vsmT + (nb*8 + g)*AST + t*8;
        uint32_t vb[8][2];
        {
            float4 c0 = *(const float4*)(vr);
            vb[0][0]=__float_as_uint(c0.x); vb[0][1]=__float_as_uint(c0.y);
            vb[1][0]=__float_as_uint(c0.z); vb[1][1]=__float_as_uint(c0.w);
        }
        if (NBV == 8) {
            float4 c1 = *(const float4*)(vr + 4);
            float4 c2 = *(const float4*)(vr + 32);
            float4 c3 = *(const float4*)(vr + 36);
            vb[2][0]=__float_as_uint(c1.x); vb[2][1]=__float_as_uint(c1.y);
            vb[3][0]=__float_as_uint(c1.z); vb[3][1]=__float_as_uint(c1.w);
            vb[4][0]=__float_as_uint(c2.x); vb[4][1]=__float_as_uint(c2.y);
            vb[5][0]=__float_as_uint(c2.z); vb[5][1]=__float_as_uint(c2.w);
            vb[6][0]=__float_as_uint(c3.x); vb[6][1]=__float_as_uint(c3.y);
            vb[7][0]=__float_as_uint(c3.z); vb[7][1]=__float_as_uint(c3.w);
        }
        #pragma unroll
        for (int kb = 0; kb < NBV; kb++) {
            mma_tf32(of[0][nb], (const uint32_t*)sf[0][kb], vb[kb]);
            mma_tf32(of[1][nb], (const uint32_t*)sf[1][kb], vb[kb]);
        }
    }
}

__global__ __launch_bounds__(128)
void attn_tc(const float* __restrict__ pk, const float* __restrict__ pv)
{
    __shared__ float ksm[64*AST];
    __shared__ float vsmT[64*AST];

    const int b = blockIdx.z, h = blockIdx.y;
    const int tid = threadIdx.x, lane = tid & 31, warp = tid >> 5;
    const int g = lane >> 2, t = lane & 3;
    const int qw = blockIdx.x*128 + warp*32;

    // Q fragments (already tf32-rounded + pre-scaled in g_q)
    const uint32_t* qsrc = (const uint32_t*)(g_q + ((size_t)(b*HH + h)*NN + qw) * DD);
    uint32_t qf[2][8][4];
    #pragma unroll
    for (int qt = 0; qt < 2; qt++)
        #pragma unroll
        for (int kx = 0; kx < 8; kx++) {
            qf[qt][kx][0] = qsrc[(qt*16 + g    )*64 + kx*8 + t    ];
            qf[qt][kx][1] = qsrc[(qt*16 + g + 8)*64 + kx*8 + t    ];
            qf[qt][kx][2] = qsrc[(qt*16 + g    )*64 + kx*8 + t + 4];
            qf[qt][kx][3] = qsrc[(qt*16 + g + 8)*64 + kx*8 + t + 4];
        }

    float of[2][8][4];
    #pragma unroll
    for (int qt = 0; qt < 2; qt++)
        #pragma unroll
        for (int nb = 0; nb < 8; nb++)
            #pragma unroll
            for (int c = 0; c < 4; c++) of[qt][nb][c] = 0.f;
    float mx[2][2] = {{-INFINITY,-INFINITY},{-INFINITY,-INFINITY}};
    float ll[2][2] = {{0.f,0.f},{0.f,0.f}};

    const float* kbase = g_k + (size_t)((b*HH + h)*NN)*DD;
    const float* vbase = g_v + (size_t)((b*HH + h)*NN)*DD;

    const int srow  = tid >> 1;         // key row 0..63
    const int shalf = tid & 1;
    const int pc = ((srow >> 5) << 5) + ((srow & 3) << 3)
                 + (((srow >> 3) & 3) << 1) + ((srow >> 2) & 1);  // perm(key)

    // --- prefix tile (16 keys, convert RNA) ---
    if (tid < 32) {
        stage_row(pk + srow*CC + h*DD + shalf*32,
                  pv + srow*CC + h*DD + shalf*32,
                  ksm, vsmT, srow, shalf, pc, true);
    }
    __syncthreads();
    attn_tile<2>(ksm, vsmT, qf, of, mx, ll, lane);

    // --- 16 full tiles ---
    for (int tile = 0; tile < 16; tile++) {
        __syncthreads();
        stage_row(kbase + (tile*64 + srow)*DD + shalf*32,
                  vbase + (tile*64 + srow)*DD + shalf*32,
                  ksm, vsmT, srow, shalf, pc, false);
        __syncthreads();
        attn_tile<8>(ksm, vsmT, qf, of, mx, ll, lane);
    }

    // --- epilogue: normalize, tf32-round, write [b,n,h,d] ---
    #pragma unroll
    for (int qt = 0; qt < 2; qt++) {
        const float i0 = 1.f / ll[qt][0], i1 = 1.f / ll[qt][1];
        const int r0 = qw + qt*16 + g, r1 = r0 + 8;
        #pragma unroll
        for (int nb = 0; nb < 8; nb++) {
            const int d = nb*8 + 2*t;
            float2 lo, hi;
            lo.x = rnd(of[qt][nb][0]*i0); lo.y = rnd(of[qt][nb][1]*i0);
            hi.x = rnd(of[qt][nb][2]*i1); hi.y = rnd(of[qt][nb][3]*i1);
            *(float2*)&g_att[((size_t)(b*NN + r0)*HH + h)*DD + d] = lo;
            *(float2*)&g_att[((size_t)(b*NN + r1)*HH + h)*DD + d] = hi;
        }
    }
}

// ---------------------------------------------------------------------------

extern "C" void kernel_launch(void* const* d_in, const int* in_sizes, int n_in,
                              void* d_out, int out_size)
{
    const float* x      = (const float*)d_in[0];
    const float* qkv_w  = (const float*)d_in[1];
    const float* qkv_b  = (const float*)d_in[2];
    const float* proj_w = (const float*)d_in[3];
    const float* proj_b = (const float*)d_in[4];
    const float* pk     = (const float*)d_in[5];
    const float* pv     = (const float*)d_in[6];
    float* out = (float*)d_out;

    cudaFuncSetAttribute(gemm_qkv_tc,  cudaFuncAttributeMaxDynamicSharedMemorySize, SMEM_GEMM);
    cudaFuncSetAttribute(gemm_proj_tc, cudaFuncAttributeMaxDynamicSharedMemorySize, SMEM_GEMM);

    float* d_xt;  cudaGetSymbolAddress((void**)&d_xt,  g_xt);
    float* d_wt;  cudaGetSymbolAddress((void**)&d_wt,  g_wt);
    float* d_pwt; cudaGetSymbolAddress((void**)&d_pwt, g_pwt);

    // pre-round inputs to tf32 (RNA) so cp.async-fed mma stays unbiased
    cvt_tf32<<<(MTOT*CC/4 + 255)/256, 256>>>((const float4*)x, (float4*)d_xt, MTOT*CC/4);
    cvt_tf32<<<(THREE_C*CC/4 + 255)/256, 256>>>((const float4*)qkv_w, (float4*)d_wt, THREE_C*CC/4);
    cvt_tf32<<<(CC*CC/4 + 255)/256, 256>>>((const float4*)proj_w, (float4*)d_pwt, CC*CC/4);

    dim3 g1(THREE_C/128, MTOT/128);      // 18 x 64
    gemm_qkv_tc<<<g1, 128, SMEM_GEMM>>>(qkv_b);

    dim3 g2(NN/128, HH, BB);             // 8 x 12 x 8
    attn_tc<<<g2, 128>>>(pk, pv);

    dim3 g3(CC/128, MTOT/128);           // 6 x 64
    gemm_proj_tc<<<g3, 128, SMEM_GEMM>>>(proj_b, out);
}